// round 10
// baseline (speedup 1.0000x reference)
#include <cuda_runtime.h>
#include <cuda_bf16.h>
#include <cstdint>

#define NPTS 100000
#define KOFF 27
#define PL 128
#define VD 16
#define NQ 432      // 27*16
#define NTOT 688    // 432 Y + 128 vf + 128 out cols
#define KP 136      // bf16 pitch for mma smem tiles (272 bytes/row)

// ---- scratch (device globals; no allocation) ----
__device__ __align__(16) float g_Y[(size_t)NPTS * NQ];
__device__ __align__(16) float g_vf[(size_t)NPTS * PL];
__device__ float g_choice[NPTS];
__device__ __align__(16) float g_Wc2[VD * PL];
__device__ float g_C[1];
// dense bf16 hi/lo W images: [NTOT][128]
__device__ __align__(16) __nv_bfloat16 g_Wih[(size_t)NTOT * 128];
__device__ __align__(16) __nv_bfloat16 g_Wil[(size_t)NTOT * 128];

// ---- warp mma.sync m16n8k16 bf16 ----
__device__ __forceinline__ void mma16816(float* c, const uint32_t* a,
                                         uint32_t b0, uint32_t b1) {
    asm volatile(
        "mma.sync.aligned.m16n8k16.row.col.f32.bf16.bf16.f32 "
        "{%0,%1,%2,%3}, {%4,%5,%6,%7}, {%8,%9}, {%0,%1,%2,%3};"
        : "+f"(c[0]), "+f"(c[1]), "+f"(c[2]), "+f"(c[3])
        : "r"(a[0]), "r"(a[1]), "r"(a[2]), "r"(a[3]), "r"(b0), "r"(b1));
}
__device__ __forceinline__ uint32_t smem_u32(const void* p) {
    uint32_t a;
    asm("{ .reg .u64 t; cvta.to.shared.u64 t, %1; cvt.u32.u64 %0, t; }" : "=r"(a) : "l"(p));
    return a;
}
__device__ __forceinline__ void cp16(uint32_t sa, const void* g) {
    asm volatile("cp.async.cg.shared.global [%0], [%1], 16;" :: "r"(sa), "l"(g) : "memory");
}
#define CP_COMMIT() asm volatile("cp.async.commit_group;" ::: "memory")
#define CP_WAIT0()  asm volatile("cp.async.wait_group 0;" ::: "memory")

// ================= prep =====================================================
__global__ void k_prep(const float* __restrict__ cb, const float* __restrict__ Wch,
                       const float* __restrict__ Wq, const float* __restrict__ Wv,
                       const float* __restrict__ Wo) {
    int b = blockIdx.x, t = threadIdx.x;
    if (b < 18) {
        for (int e = t; e < 5120; e += 256) {
            int idx = b * 5120 + e;
            if (idx >= NTOT * 128) break;
            int n = idx >> 7, k = idx & 127;
            float v;
            if (n < NQ)            v = Wq[(size_t)(n >> 4) * 2048 + k * 16 + (n & 15)];
            else if (n < NQ + 128) v = Wv[(size_t)k * 128 + (n - NQ)];
            else                   v = Wo[(size_t)k * 128 + (n - NQ - 128)];
            __nv_bfloat16 hi = __float2bfloat16(v);
            __nv_bfloat16 lo = __float2bfloat16(v - __bfloat162float(hi));
            g_Wih[(size_t)n * 128 + k] = hi;
            g_Wil[(size_t)n * 128 + k] = lo;
        }
    } else {
        for (int e = t; e < VD * PL; e += 256) {
            int v = e >> 7, o = e & 127;
            float s = 0.f;
#pragma unroll
            for (int r = 0; r < 8; ++r) s += cb[8 * v + r] * Wch[(8 * v + r) * PL + o];
            g_Wc2[e] = s;
        }
        if (t == 0) {
            float c = 0.f;
            for (int i = 0; i < PL; ++i) c += cb[i] * cb[i];
            g_C[0] = c;
        }
    }
}

// ---- shared device helpers ----
__device__ __forceinline__ void build_A(const float* __restrict__ src, int i0,
                                        __nv_bfloat16* Ah, __nv_bfloat16* Al, int t) {
    for (int e = t; e < 2048; e += 256) {
        int m = e >> 4, kb = e & 15;
        int gi = i0 + m;
        float xs[8];
        if (gi < NPTS) {
            float4 a = ((const float4*)src)[(size_t)gi * 32 + kb * 2];
            float4 b = ((const float4*)src)[(size_t)gi * 32 + kb * 2 + 1];
            xs[0] = a.x; xs[1] = a.y; xs[2] = a.z; xs[3] = a.w;
            xs[4] = b.x; xs[5] = b.y; xs[6] = b.z; xs[7] = b.w;
        } else {
#pragma unroll
            for (int j = 0; j < 8; ++j) xs[j] = 0.f;
        }
        union { __nv_bfloat16 h[8]; uint4 v; } uh, ul;
#pragma unroll
        for (int j = 0; j < 8; ++j) {
            __nv_bfloat16 hi = __float2bfloat16(xs[j]);
            uh.h[j] = hi;
            ul.h[j] = __float2bfloat16(xs[j] - __bfloat162float(hi));
        }
        *(uint4*)((char*)Ah + m * (KP * 2) + kb * 16) = uh.v;
        *(uint4*)((char*)Al + m * (KP * 2) + kb * 16) = ul.v;
    }
}
__device__ __forceinline__ void load_Afrag(const __nv_bfloat16* A, int row0,
                                           int gr, int cq, uint32_t f[8][4]) {
    const char* r0 = (const char*)A + (row0 + gr) * (KP * 2);
#pragma unroll
    for (int k = 0; k < 8; ++k) {
        int k0 = k * 16;
        f[k][0] = *(const uint32_t*)(r0 + (k0 + cq) * 2);
        f[k][1] = *(const uint32_t*)(r0 + 8 * (KP * 2) + (k0 + cq) * 2);
        f[k][2] = *(const uint32_t*)(r0 + (k0 + cq + 8) * 2);
        f[k][3] = *(const uint32_t*)(r0 + 8 * (KP * 2) + (k0 + cq + 8) * 2);
    }
}

// ================= split-bf16 mma.sync Y + vf GEMM (cp.async dbl-buffer) ====
__global__ __launch_bounds__(256) void k_mmaYV(
        const float* __restrict__ x, const float* __restrict__ vg,
        const float* __restrict__ vb, const float* __restrict__ coords,
        const float* __restrict__ Wpos, const float* __restrict__ bpos) {
    extern __shared__ __align__(16) char smem[];
    __nv_bfloat16* Ah = (__nv_bfloat16*)smem;            // 128*KP
    __nv_bfloat16* Al = Ah + 128 * KP;
    __nv_bfloat16* Wb[2][2];                             // [buf][hi/lo], 112*KP each
    Wb[0][0] = Al + 128 * KP;
    Wb[0][1] = Wb[0][0] + 112 * KP;
    Wb[1][0] = Wb[0][1] + 112 * KP;
    Wb[1][1] = Wb[1][0] + 112 * KP;
    float* pos_s = (float*)(Wb[1][1] + 112 * KP);        // [128][16]
    int t = threadIdx.x, lane = t & 31, w = t >> 5;
    int i0 = blockIdx.x * 128;

    // issue W chunk c into buffer bi via cp.async
    auto issueW = [&](int c, int bi) {
        uint32_t dh = smem_u32(Wb[bi][0]), dl = smem_u32(Wb[bi][1]);
        for (int e = t; e < 112 * 16; e += 256) {
            int row = e >> 4, q = e & 15;
            size_t gof = (size_t)(c * 112 + row) * 256 + q * 16;
            uint32_t so = (uint32_t)(row * (KP * 2) + q * 16);
            cp16(dh + so, (const char*)g_Wih + gof);
            cp16(dl + so, (const char*)g_Wil + gof);
        }
        CP_COMMIT();
    };

    issueW(0, 0);
    build_A(x, i0, Ah, Al, t);
    for (int e = t; e < 2048; e += 256) {
        int m = e >> 4, ng = e & 15;
        int gi = i0 + m;
        float p = 0.f;
        if (gi < NPTS) {
            float cx = coords[(size_t)gi * 3], cy = coords[(size_t)gi * 3 + 1],
                  cz = coords[(size_t)gi * 3 + 2];
            p = cx * Wpos[ng] + cy * Wpos[16 + ng] + cz * Wpos[32 + ng] + bpos[ng];
        }
        pos_s[e] = p;
    }
    CP_WAIT0();
    __syncthreads();

    int gr = lane >> 2, cq = (lane & 3) * 2;
    uint32_t ahf[8][4], alf[8][4];
    load_Afrag(Ah, w * 16, gr, cq, ahf);
    load_Afrag(Al, w * 16, gr, cq, alf);

    int gi0 = i0 + w * 16 + gr, gi1 = gi0 + 8;

    for (int c = 0; c < 5; ++c) {
        if (c < 4) issueW(c + 1, (c + 1) & 1);
        const __nv_bfloat16* Wh = Wb[c & 1][0];
        const __nv_bfloat16* Wl = Wb[c & 1][1];

#pragma unroll 2
        for (int nt = 0; nt < 14; ++nt) {
            int nc = c * 112 + nt * 8;
            const char* Bh = (const char*)Wh + (nt * 8 + gr) * (KP * 2) + cq * 2;
            const char* Bl = (const char*)Wl + (nt * 8 + gr) * (KP * 2) + cq * 2;
            float a1[4] = {0.f, 0.f, 0.f, 0.f};
            float a2[4] = {0.f, 0.f, 0.f, 0.f};
            float a3[4] = {0.f, 0.f, 0.f, 0.f};
#pragma unroll
            for (int k = 0; k < 8; ++k) {
                int kb = k * 32;
                uint32_t bh0 = *(const uint32_t*)(Bh + kb);
                uint32_t bh1 = *(const uint32_t*)(Bh + kb + 16);
                uint32_t bl0 = *(const uint32_t*)(Bl + kb);
                uint32_t bl1 = *(const uint32_t*)(Bl + kb + 16);
                mma16816(a1, ahf[k], bh0, bh1);
                mma16816(a2, alf[k], bh0, bh1);
                mma16816(a3, ahf[k], bl0, bl1);
            }
            float acc[4];
#pragma unroll
            for (int q = 0; q < 4; ++q) acc[q] = a1[q] + (a2[q] + a3[q]);
            if (nc < NQ) {
                if (gi0 < NPTS)
                    *(float2*)(g_Y + (size_t)gi0 * NQ + nc + cq) = make_float2(acc[0], acc[1]);
                if (gi1 < NPTS)
                    *(float2*)(g_Y + (size_t)gi1 * NQ + nc + cq) = make_float2(acc[2], acc[3]);
            } else {
                int v = nc - NQ + cq;
                float g0 = vg[v], g1 = vg[v + 1], b0 = vb[v], b1 = vb[v + 1];
                if (gi0 < NPTS) {
                    float p = pos_s[(w * 16 + gr) * 16 + (v >> 3)];
                    *(float2*)(g_vf + (size_t)gi0 * PL + v) = make_float2(
                        fmaxf(acc[0] * g0 + b0, 0.f) + p, fmaxf(acc[1] * g1 + b1, 0.f) + p);
                }
                if (gi1 < NPTS) {
                    float p = pos_s[(w * 16 + gr + 8) * 16 + (v >> 3)];
                    *(float2*)(g_vf + (size_t)gi1 * PL + v) = make_float2(
                        fmaxf(acc[2] * g0 + b0, 0.f) + p, fmaxf(acc[3] * g1 + b1, 0.f) + p);
                }
            }
        }
        CP_WAIT0();
        __syncthreads();
    }
}

// ================= masked gather of Y + BN/relu + choice ====================
__global__ void k_qg(const int* __restrict__ nidx, const int* __restrict__ nmask,
                     const float* __restrict__ qg, const float* __restrict__ qb,
                     const float* __restrict__ bch) {
    __shared__ float wc[2048];
    __shared__ float bs[128];
    int t = threadIdx.x;
    for (int e = t; e < 2048; e += 256) wc[e] = g_Wc2[e];
    for (int e = t; e < 128; e += 256) bs[e] = bch[e];
    __syncthreads();
    int lane = t & 31, w = t >> 5;
    int i = blockIdx.x * 8 + w;
    if (i >= NPTS) return;
    int v = lane & 15, h = lane >> 4;

    float qp = 0.f;
#pragma unroll
    for (int tt = 0; tt < 14; ++tt) {
        int k = 2 * tt + h;
        bool ok = (k < KOFF);
        int m = ok ? nmask[(size_t)k * NPTS + i] : 0;
        int j = ok ? nidx[(size_t)k * NPTS + i] : 0;
        float val = m ? g_Y[(size_t)j * NQ + k * 16 + v] : 0.f;
        qp += val;
    }
    qp += __shfl_xor_sync(0xffffffffu, qp, 16);
    float qf = fmaxf(qp * qg[v] + qb[v], 0.f);
    float qa[16];
#pragma unroll
    for (int vv = 0; vv < 16; ++vv) qa[vv] = __shfl_sync(0xffffffffu, qf, vv);

    float4 av = ((const float4*)bs)[lane];
#pragma unroll
    for (int vv = 0; vv < 16; ++vv) {
        float4 wv4 = *(const float4*)(wc + vv * 128 + lane * 4);
        av.x += qa[vv] * wv4.x; av.y += qa[vv] * wv4.y;
        av.z += qa[vv] * wv4.z; av.w += qa[vv] * wv4.w;
    }
    float s = fmaxf(av.x, 0.f) + fmaxf(av.y, 0.f) + fmaxf(av.z, 0.f) + fmaxf(av.w, 0.f);
#pragma unroll
    for (int d = 16; d; d >>= 1) s += __shfl_xor_sync(0xffffffffu, s, d);
    if (lane == 0) g_choice[i] = s;
}

// ================= fused attention + out GEMM ===============================
// Phase 1: per warp, 16 points: softmax over rank-1 scores, gather-weighted sum
//          of v_f, write bf16 hi/lo directly into the A tile in smem.
// Phase 2: out = relu((A@Wo)*g+b) + x via split-bf16 mma.sync.
__global__ __launch_bounds__(256) void k_attnO(
        const int* __restrict__ nidx, const int* __restrict__ nmask,
        const float* __restrict__ ogm, const float* __restrict__ obt,
        const float* __restrict__ resid, float* __restrict__ Out) {
    extern __shared__ __align__(16) char smem[];
    __nv_bfloat16* Ah = (__nv_bfloat16*)smem;
    __nv_bfloat16* Al = Ah + 128 * KP;
    __nv_bfloat16* Wh = Al + 128 * KP;   // 128*KP
    __nv_bfloat16* Wl = Wh + 128 * KP;
    int t = threadIdx.x, lane = t & 31, w = t >> 5;
    int i0 = blockIdx.x * 128;

    // stage W_out (image rows 560..687)
    for (int e = t; e < 128 * 16; e += 256) {
        int row = e >> 4, q = e & 15;
        size_t gsrc = ((size_t)(560 + row) * 256 + q * 16) >> 4;
        *(uint4*)((char*)Wh + row * (KP * 2) + q * 16) = ((const uint4*)g_Wih)[gsrc];
        *(uint4*)((char*)Wl + row * (KP * 2) + q * 16) = ((const uint4*)g_Wil)[gsrc];
    }

    // ---- phase 1: attention ----
    float C = g_C[0];
    for (int p = 0; p < 16; ++p) {
        int mrow = w * 16 + p;
        int i = i0 + mrow;
        float4 acc = {0.f, 0.f, 0.f, 0.f};
        if (i < NPTS) {
            float tC = C * g_choice[i];
            int m = 0, j = 0;
            float s = -1e9f;
            if (lane < KOFF) {
                m = nmask[(size_t)lane * NPTS + i];
                j = nidx[(size_t)lane * NPTS + i];
                s = m ? tC * g_choice[j] : -1e9f;
            }
            float mx = s;
#pragma unroll
            for (int d = 16; d; d >>= 1) mx = fmaxf(mx, __shfl_xor_sync(0xffffffffu, mx, d));
            float e = (lane < KOFF && m) ? expf(s - mx) : 0.f;
            float se = e;
#pragma unroll
            for (int d = 16; d; d >>= 1) se += __shfl_xor_sync(0xffffffffu, se, d);
            float a = e / se;
#pragma unroll
            for (int k = 0; k < KOFF; ++k) {
                float ak = __shfl_sync(0xffffffffu, a, k);
                int jk = __shfl_sync(0xffffffffu, j, k);
                int mk = __shfl_sync(0xffffffffu, m, k);
                if (mk) {
                    float4 v = ((const float4*)g_vf)[(size_t)jk * 32 + lane];
                    acc.x += ak * v.x; acc.y += ak * v.y;
                    acc.z += ak * v.z; acc.w += ak * v.w;
                }
            }
        }
        float av4[4] = {acc.x, acc.y, acc.z, acc.w};
        union { __nv_bfloat16 h[4]; uint2 u; } hh, ll;
#pragma unroll
        for (int jj = 0; jj < 4; ++jj) {
            __nv_bfloat16 hi = __float2bfloat16(av4[jj]);
            hh.h[jj] = hi;
            ll.h[jj] = __float2bfloat16(av4[jj] - __bfloat162float(hi));
        }
        *(uint2*)((char*)Ah + mrow * (KP * 2) + lane * 8) = hh.u;
        *(uint2*)((char*)Al + mrow * (KP * 2) + lane * 8) = ll.u;
    }
    __syncthreads();

    // ---- phase 2: GEMM ----
    int gr = lane >> 2, cq = (lane & 3) * 2;
    uint32_t ahf[8][4], alf[8][4];
    load_Afrag(Ah, w * 16, gr, cq, ahf);
    load_Afrag(Al, w * 16, gr, cq, alf);

    int gi0 = i0 + w * 16 + gr, gi1 = gi0 + 8;

#pragma unroll 2
    for (int nt = 0; nt < 16; ++nt) {
        int nc = nt * 8;
        const char* Bh = (const char*)Wh + (nt * 8 + gr) * (KP * 2) + cq * 2;
        const char* Bl = (const char*)Wl + (nt * 8 + gr) * (KP * 2) + cq * 2;
        float a1[4] = {0.f, 0.f, 0.f, 0.f};
        float a2[4] = {0.f, 0.f, 0.f, 0.f};
        float a3[4] = {0.f, 0.f, 0.f, 0.f};
#pragma unroll
        for (int k = 0; k < 8; ++k) {
            int kb = k * 32;
            uint32_t bh0 = *(const uint32_t*)(Bh + kb);
            uint32_t bh1 = *(const uint32_t*)(Bh + kb + 16);
            uint32_t bl0 = *(const uint32_t*)(Bl + kb);
            uint32_t bl1 = *(const uint32_t*)(Bl + kb + 16);
            mma16816(a1, ahf[k], bh0, bh1);
            mma16816(a2, alf[k], bh0, bh1);
            mma16816(a3, ahf[k], bl0, bl1);
        }
        int v = nc + cq;
        float g0 = ogm[v], g1 = ogm[v + 1], b0 = obt[v], b1 = obt[v + 1];
        if (gi0 < NPTS) {
            float2 r = *(const float2*)(resid + (size_t)gi0 * PL + v);
            *(float2*)(Out + (size_t)gi0 * PL + v) = make_float2(
                fmaxf((a1[0] + (a2[0] + a3[0])) * g0 + b0, 0.f) + r.x,
                fmaxf((a1[1] + (a2[1] + a3[1])) * g1 + b1, 0.f) + r.y);
        }
        if (gi1 < NPTS) {
            float2 r = *(const float2*)(resid + (size_t)gi1 * PL + v);
            *(float2*)(Out + (size_t)gi1 * PL + v) = make_float2(
                fmaxf((a1[2] + (a2[2] + a3[2])) * g0 + b0, 0.f) + r.x,
                fmaxf((a1[3] + (a2[3] + a3[3])) * g1 + b1, 0.f) + r.y);
        }
    }
}

// ================= launch ====================================================
extern "C" void kernel_launch(void* const* d_in, const int* in_sizes, int n_in,
                              void* d_out, int out_size) {
    const float* x      = (const float*)d_in[0];
    const float* coords = (const float*)d_in[1];
    const float* Wq     = (const float*)d_in[2];
    const float* qg     = (const float*)d_in[3];
    const float* qb     = (const float*)d_in[4];
    const float* Wv     = (const float*)d_in[5];
    const float* vg     = (const float*)d_in[6];
    const float* vb     = (const float*)d_in[7];
    const float* cb     = (const float*)d_in[8];
    const float* Wch    = (const float*)d_in[9];
    const float* bch    = (const float*)d_in[10];
    const float* Wpos   = (const float*)d_in[11];
    const float* bpos   = (const float*)d_in[12];
    const float* Wo     = (const float*)d_in[13];
    const float* ogm    = (const float*)d_in[14];
    const float* obt    = (const float*)d_in[15];
    const int*   nidx   = (const int*)d_in[16];
    const int*   nmask  = (const int*)d_in[17];
    float* out = (float*)d_out;

    size_t smYV = (size_t)(2 * 128 * KP * 2) + (size_t)(4 * 112 * KP * 2) + 128 * 16 * 4;
    size_t smAO = (size_t)(4 * 128 * KP * 2);
    cudaFuncSetAttribute(k_mmaYV, cudaFuncAttributeMaxDynamicSharedMemorySize, (int)smYV);
    cudaFuncSetAttribute(k_attnO, cudaFuncAttributeMaxDynamicSharedMemorySize, (int)smAO);

    int mblocks = (NPTS + 127) / 128;  // 782

    k_prep<<<19, 256>>>(cb, Wch, Wq, Wv, Wo);
    k_mmaYV<<<mblocks, 256, smYV>>>(x, vg, vb, coords, Wpos, bpos);
    k_qg<<<(NPTS + 7) / 8, 256>>>(nidx, nmask, qg, qb, bch);
    k_attnO<<<mblocks, 256, smAO>>>(nidx, nmask, ogm, obt, x, out);
}